// round 8
// baseline (speedup 1.0000x reference)
#include <cuda_runtime.h>
#include <cuda_fp16.h>
#include <cuda_fp8.h>
#include <math.h>
#include <stdint.h>

#define BB  8
#define TT  2048
#define CH  1024

#define NTC   (BB * TT * CH)              // 16,777,216
#define NTT   ((size_t)BB * TT * TT)      // 33,554,432

// ---------------- scratch (no allocations allowed) ----------------
__device__ uint8_t g_hQ8[NTC];            // fp8 Q
__device__ uint8_t g_hK8[NTC];            // fp8 K
__device__ __half  g_hKT[NTC];            // f16 per-batch [CH][TT]
__device__ uint8_t g_uT8 [CH * CH];       // fp8 u^T
__device__ __half  g_hW1T[CH * CH];
__device__ __half  g_hW2T[CH * CH];
__device__ uint8_t g_f1q[NTC];            // fp8 relu(Qu)*d
__device__ uint8_t g_f2q[NTC];            // fp8 relu(Ku)
__device__ __half  g_hS [NTT];            // f16 exp(scores)
__device__ float   g_part[BB * TT * 8];
__device__ float   g_invs[BB * TT];
__device__ float   g_ctx[NTC];
__device__ __half  g_hLN[NTC];
__device__ __half  g_hH [NTC];

enum { EPI_PROJ = 0, EPI_EXP, EPI_CTX, EPI_BIAS_RELU, EPI_BIAS };

// ---------------- PTX helpers ----------------
__device__ __forceinline__ uint32_t smem_u32(const void* p) {
    uint32_t a;
    asm("{ .reg .u64 t; cvta.to.shared.u64 t, %1; cvt.u32.u64 %0, t; }" : "=r"(a) : "l"(p));
    return a;
}
__device__ __forceinline__ void ldsm4(uint32_t* r, uint32_t addr) {
    asm volatile("ldmatrix.sync.aligned.m8n8.x4.shared.b16 {%0,%1,%2,%3}, [%4];"
        : "=r"(r[0]), "=r"(r[1]), "=r"(r[2]), "=r"(r[3]) : "r"(addr));
}
__device__ __forceinline__ void mma_f16(float* d, const uint32_t* a, const uint32_t* b) {
    asm volatile(
        "mma.sync.aligned.m16n8k16.row.col.f32.f16.f16.f32 "
        "{%0,%1,%2,%3}, {%4,%5,%6,%7}, {%8,%9}, {%0,%1,%2,%3};"
        : "+f"(d[0]), "+f"(d[1]), "+f"(d[2]), "+f"(d[3])
        : "r"(a[0]), "r"(a[1]), "r"(a[2]), "r"(a[3]), "r"(b[0]), "r"(b[1]));
}
__device__ __forceinline__ void mma_e4m3(float* d, const uint32_t* a, const uint32_t* b) {
    asm volatile(
        "mma.sync.aligned.m16n8k32.row.col.f32.e4m3.e4m3.f32 "
        "{%0,%1,%2,%3}, {%4,%5,%6,%7}, {%8,%9}, {%0,%1,%2,%3};"
        : "+f"(d[0]), "+f"(d[1]), "+f"(d[2]), "+f"(d[3])
        : "r"(a[0]), "r"(a[1]), "r"(a[2]), "r"(a[3]), "r"(b[0]), "r"(b[1]));
}
// pack two floats -> e4m3x2, byte0 = lo, byte1 = hi
__device__ __forceinline__ uint16_t pack8(float lo, float hi) {
    uint16_t r;
    asm("cvt.rn.satfinite.e4m3x2.f32 %0, %1, %2;" : "=h"(r) : "f"(hi), "f"(lo));
    return r;
}
#define CP16(dst, src) \
    asm volatile("cp.async.cg.shared.global [%0], [%1], 16;" :: "r"(dst), "l"(src) : "memory")
#define CP_COMMIT()  asm volatile("cp.async.commit_group;" ::: "memory")
#define CP_WAIT1()   asm volatile("cp.async.wait_group 1;" ::: "memory")
#define CP_WAIT0()   asm volatile("cp.async.wait_group 0;" ::: "memory")

// swizzled offset within a tile: rows of 64B, 16B column c (0..3)
__device__ __forceinline__ uint32_t swz(int row, int c) {
    return (uint32_t)(row * 64 + (((c) ^ ((row >> 1) & 3)) << 4));
}

// CTA tile 128x256, 3-stage cp.async ring, 16 warps (4m x 4n) of 32x64.
// Tile rows are 64 BYTES: f16 -> K-tile 32 elems; fp8 -> K-tile 64 elems.
#define BM 128
#define BN 256
#define A_BYTES (BM * 64)                 // 8192
#define B_BYTES (BN * 64)                 // 16384
#define STG     (A_BYTES + B_BYTES)       // 24576
#define SMEM_G  (3 * STG)                 // 73728
#define NTHR    512

// =========== shared mainloop macro-body via include-like templates ===========
// (two kernels below share structure; fp8 differs in element size, loop count, mma)

// ---------------- f16 GEMM: C = A[M][K] * B[N][K]^T ----------------
template <int EPI, bool OUTH>
__global__ void __launch_bounds__(NTHR, 1)
gemmv5(const __half* __restrict__ A, const __half* __restrict__ B,
       void* __restrict__ Cv,
       int M, int N, int K, long sA, long sB, long sC,
       const float* __restrict__ vec, long sVec,
       const float* __restrict__ add, long sAdd, float scale)
{
    extern __shared__ char smem[];
    const uint32_t sb = smem_u32(smem);
    const int tid = threadIdx.x, lane = tid & 31, warp = tid >> 5;
    const int wm = warp >> 2, wn = warp & 3;
    const int z = blockIdx.z;

    const __half* Ap = A + (long)z * sA + (long)(blockIdx.y * BM) * K;
    const __half* Bp = B + (long)z * sB + (long)(blockIdx.x * BN) * K;

    uint32_t adst, bdst[2];
    const __half* asrc;
    const __half* bsrc[2];
    {
        int r = tid >> 2, c = tid & 3;
        adst = swz(r, c);
        asrc = Ap + (long)r * K + c * 8;
    }
#pragma unroll
    for (int i = 0; i < 2; i++) {
        int q = tid + i * NTHR, r = q >> 2, c = q & 3;
        bdst[i] = A_BYTES + swz(r, c);
        bsrc[i] = Bp + (long)r * K + c * 8;
    }

#define ISSUE(kt)                                                              \
    do {                                                                       \
        const uint32_t _s = sb + ((kt) % 3) * STG;                             \
        const long _ko = (long)(kt) * 32;                                      \
        CP16(_s + adst, asrc + _ko);                                           \
        CP16(_s + bdst[0], bsrc[0] + _ko);                                     \
        CP16(_s + bdst[1], bsrc[1] + _ko);                                     \
        CP_COMMIT();                                                           \
    } while (0)

    const int q8 = lane >> 3, rr = lane & 7;
    const int rA = wm * 32 + (q8 & 1) * 8 + rr;
    const int xA = (rA >> 1) & 3;
    const int cA = q8 >> 1;
    const int rB = wn * 64 + (q8 >> 1) * 8 + rr;
    const int xB = (rB >> 1) & 3;
    const int cB = q8 & 1;

    float acc[2][8][4];
#pragma unroll
    for (int mi = 0; mi < 2; mi++)
#pragma unroll
        for (int ni = 0; ni < 8; ni++)
#pragma unroll
            for (int e = 0; e < 4; e++) acc[mi][ni][e] = 0.f;

    ISSUE(0);
    ISSUE(1);

    const int nCh = K / 32;
    for (int kt = 0; kt < nCh; kt++) {
        if (kt + 1 < nCh) CP_WAIT1(); else CP_WAIT0();
        __syncthreads();
        const uint32_t sbase = sb + (kt % 3) * STG;
#pragma unroll
        for (int s = 0; s < 2; s++) {
            uint32_t af[2][4];
#pragma unroll
            for (int mi = 0; mi < 2; mi++)
                ldsm4(af[mi], sbase + (uint32_t)((rA + mi * 16) * 64) +
                              (uint32_t)((((2 * s + cA) ^ xA)) << 4));
#pragma unroll
            for (int nip = 0; nip < 4; nip++) {
                uint32_t t4[4];
                ldsm4(t4, sbase + A_BYTES + (uint32_t)((rB + nip * 16) * 64) +
                          (uint32_t)((((2 * s + cB) ^ xB)) << 4));
#pragma unroll
                for (int mi = 0; mi < 2; mi++) mma_f16(acc[mi][2 * nip],     af[mi], &t4[0]);
#pragma unroll
                for (int mi = 0; mi < 2; mi++) mma_f16(acc[mi][2 * nip + 1], af[mi], &t4[2]);
            }
        }
        if (kt + 2 < nCh) ISSUE(kt + 2);
    }
#undef ISSUE

    const float* vv = vec ? vec + (long)z * sVec : nullptr;
    const float* adb = add ? add + (long)z * sAdd : nullptr;
    const long cBase = (long)z * sC;

#pragma unroll
    for (int mi = 0; mi < 2; mi++) {
        const int r0 = blockIdx.y * BM + wm * 32 + mi * 16 + (lane >> 2);
        float rowS[2];
        if (EPI == EPI_CTX) { rowS[0] = vv[r0]; rowS[1] = vv[r0 + 8]; }
#pragma unroll
        for (int ni = 0; ni < 8; ni++) {
            const int c = blockIdx.x * BN + wn * 64 + ni * 8 + (lane & 3) * 2;
#pragma unroll
            for (int p = 0; p < 2; p++) {
                const int r = r0 + p * 8;
                float v0 = acc[mi][ni][p * 2 + 0];
                float v1 = acc[mi][ni][p * 2 + 1];
                if (EPI == EPI_CTX) {
                    float2 a2 = *(const float2*)(adb + (long)r * N + c);
                    v0 = v0 * rowS[p] + a2.x;
                    v1 = v1 * rowS[p] + a2.y;
                }
                if (EPI == EPI_BIAS_RELU) { v0 = fmaxf(v0 + vv[c], 0.f); v1 = fmaxf(v1 + vv[c + 1], 0.f); }
                if (EPI == EPI_BIAS)      { v0 += vv[c]; v1 += vv[c + 1]; }
                if (OUTH) {
                    __half* op = (__half*)Cv + cBase + (long)r * N + c;
                    *(__half2*)op = __floats2half2_rn(v0, v1);
                } else {
                    float* op = (float*)Cv + cBase + (long)r * N + c;
                    *(float2*)op = make_float2(v0, v1);
                }
            }
        }
    }
}

// ---------------- fp8 GEMM: C = A[M][K] * B[N][K]^T, e4m3 in, fp32 acc ----------------
template <int EPI>
__global__ void __launch_bounds__(NTHR, 1)
gemm8(const uint8_t* __restrict__ A, const uint8_t* __restrict__ A2,
      const uint8_t* __restrict__ B, void* __restrict__ Cv, void* __restrict__ Cv2,
      int M, int N, int K, long sA, long sB, long sC,
      const float* __restrict__ vec, long sVec, float scale,
      float* __restrict__ part)
{
    extern __shared__ char smem[];
    const uint32_t sb = smem_u32(smem);
    const int tid = threadIdx.x, lane = tid & 31, warp = tid >> 5;
    const int wm = warp >> 2, wn = warp & 3;
    const int z = blockIdx.z;

    const uint8_t* Abase = A;
    void* Cbase = Cv;
    if (EPI == EPI_PROJ && z == 1) { Abase = A2; Cbase = Cv2; }

    const uint8_t* Ap = Abase + (long)z * sA + (long)(blockIdx.y * BM) * K;
    const uint8_t* Bp = B + (long)z * sB + (long)(blockIdx.x * BN) * K;

    uint32_t adst, bdst[2];
    const uint8_t* asrc;
    const uint8_t* bsrc[2];
    {
        int r = tid >> 2, c = tid & 3;
        adst = swz(r, c);
        asrc = Ap + (long)r * K + c * 16;
    }
#pragma unroll
    for (int i = 0; i < 2; i++) {
        int q = tid + i * NTHR, r = q >> 2, c = q & 3;
        bdst[i] = A_BYTES + swz(r, c);
        bsrc[i] = Bp + (long)r * K + c * 16;
    }

#define ISSUE8(kt)                                                             \
    do {                                                                       \
        const uint32_t _s = sb + ((kt) % 3) * STG;                             \
        const long _ko = (long)(kt) * 64;                                      \
        CP16(_s + adst, asrc + _ko);                                           \
        CP16(_s + bdst[0], bsrc[0] + _ko);                                     \
        CP16(_s + bdst[1], bsrc[1] + _ko);                                     \
        CP_COMMIT();                                                           \
    } while (0)

    const int q8 = lane >> 3, rr = lane & 7;
    const int rA = wm * 32 + (q8 & 1) * 8 + rr;
    const int xA = (rA >> 1) & 3;
    const int cA = q8 >> 1;
    const int rB = wn * 64 + (q8 >> 1) * 8 + rr;
    const int xB = (rB >> 1) & 3;
    const int cB = q8 & 1;

    float acc[2][8][4];
#pragma unroll
    for (int mi = 0; mi < 2; mi++)
#pragma unroll
        for (int ni = 0; ni < 8; ni++)
#pragma unroll
            for (int e = 0; e < 4; e++) acc[mi][ni][e] = 0.f;

    ISSUE8(0);
    ISSUE8(1);

    const int nCh = K / 64;                       // 64 fp8 elems per tile row
    for (int kt = 0; kt < nCh; kt++) {
        if (kt + 1 < nCh) CP_WAIT1(); else CP_WAIT0();
        __syncthreads();
        const uint32_t sbase = sb + (kt % 3) * STG;
#pragma unroll
        for (int s = 0; s < 2; s++) {             // k32 per step
            uint32_t af[2][4];
#pragma unroll
            for (int mi = 0; mi < 2; mi++)
                ldsm4(af[mi], sbase + (uint32_t)((rA + mi * 16) * 64) +
                              (uint32_t)((((2 * s + cA) ^ xA)) << 4));
#pragma unroll
            for (int nip = 0; nip < 4; nip++) {
                uint32_t t4[4];
                ldsm4(t4, sbase + A_BYTES + (uint32_t)((rB + nip * 16) * 64) +
                          (uint32_t)((((2 * s + cB) ^ xB)) << 4));
#pragma unroll
                for (int mi = 0; mi < 2; mi++) mma_e4m3(acc[mi][2 * nip],     af[mi], &t4[0]);
#pragma unroll
                for (int mi = 0; mi < 2; mi++) mma_e4m3(acc[mi][2 * nip + 1], af[mi], &t4[2]);
            }
        }
        if (kt + 2 < nCh) ISSUE8(kt + 2);
    }
#undef ISSUE8

    const float* vv = vec ? vec + (long)z * sVec : nullptr;
    const long cBase = (long)z * sC;

    if (EPI == EPI_EXP) {
        float rsl[2][2] = {{0.f, 0.f}, {0.f, 0.f}};
#pragma unroll
        for (int mi = 0; mi < 2; mi++) {
            const int r0 = blockIdx.y * BM + wm * 32 + mi * 16 + (lane >> 2);
#pragma unroll
            for (int ni = 0; ni < 8; ni++) {
                const int c = blockIdx.x * BN + wn * 64 + ni * 8 + (lane & 3) * 2;
                const float m0 = vv[c], m1 = vv[c + 1];
#pragma unroll
                for (int p = 0; p < 2; p++) {
                    const int r = r0 + p * 8;
                    float e0 = (m0 == 0.f) ? 0.f : expf(acc[mi][ni][p * 2 + 0] * scale);
                    float e1 = (m1 == 0.f) ? 0.f : expf(acc[mi][ni][p * 2 + 1] * scale);
                    __half2 h = __floats2half2_rn(e0, e1);
                    *(__half2*)((__half*)Cv + cBase + (long)r * N + c) = h;
                    float2 fr = __half22float2(h);
                    rsl[mi][p] += fr.x + fr.y;
                }
            }
        }
        float* rsf = (float*)(smem + (nCh % 3) * STG);
#pragma unroll
        for (int mi = 0; mi < 2; mi++)
#pragma unroll
            for (int p = 0; p < 2; p++) {
                float s = rsl[mi][p];
                s += __shfl_xor_sync(0xffffffffu, s, 1);
                s += __shfl_xor_sync(0xffffffffu, s, 2);
                if ((lane & 3) == 0)
                    rsf[(wm * 32 + mi * 16 + p * 8 + (lane >> 2)) * 4 + wn] = s;
            }
        __syncthreads();
        if (tid < BM) {
            float s = rsf[tid * 4] + rsf[tid * 4 + 1] + rsf[tid * 4 + 2] + rsf[tid * 4 + 3];
            part[((long)z * TT + blockIdx.y * BM + tid) * 8 + blockIdx.x] = s;
        }
        return;
    }

    // EPI_PROJ: relu (and *diag for z==0), output fp8
#pragma unroll
    for (int mi = 0; mi < 2; mi++) {
        const int r0 = blockIdx.y * BM + wm * 32 + mi * 16 + (lane >> 2);
#pragma unroll
        for (int ni = 0; ni < 8; ni++) {
            const int c = blockIdx.x * BN + wn * 64 + ni * 8 + (lane & 3) * 2;
#pragma unroll
            for (int p = 0; p < 2; p++) {
                const int r = r0 + p * 8;
                float v0 = fmaxf(acc[mi][ni][p * 2 + 0], 0.f);
                float v1 = fmaxf(acc[mi][ni][p * 2 + 1], 0.f);
                if (z == 0) { v0 *= vv[c]; v1 *= vv[c + 1]; }
                *(uint16_t*)((uint8_t*)Cbase + cBase + (long)r * N + c) = pack8(v0, v1);
            }
        }
    }
}

// ---------------- invs: qmask/rowsum ----------------
__global__ __launch_bounds__(256)
void invs_k(const float* __restrict__ part, const float* __restrict__ qmask,
            float* __restrict__ invs)
{
    const int i = blockIdx.x * 256 + threadIdx.x;
    float s = 0.f;
#pragma unroll
    for (int j = 0; j < 8; j++) s += part[(long)i * 8 + j];
    invs[i] = qmask[i] / s;
}

// ---------------- Q convert: f32 -> fp8, plus fp32 copy to output ----------------
__global__ __launch_bounds__(256)
void convq_k(const float* __restrict__ in, uint8_t* __restrict__ out, float* __restrict__ outc)
{
    const int i = blockIdx.x * 256 + threadIdx.x;
    float4 v = ((const float4*)in)[i];
    uint32_t u = (uint32_t)pack8(v.x, v.y) | ((uint32_t)pack8(v.z, v.w) << 16);
    ((uint32_t*)out)[i] = u;
    ((float4*)outc)[i] = v;
}

// ---------------- K convert + transpose: f32 [R][C] -> fp8 linear + f16 [C][R] ----------------
__global__ __launch_bounds__(256)
void convkt_k(const float* __restrict__ in, uint8_t* __restrict__ lin, __half* __restrict__ tr,
              int R, int C, long sIn, long sOut)
{
    __shared__ float t[32][33];
    const long zi = (long)blockIdx.z * sIn, zo = (long)blockIdx.z * sOut;
    const int c0 = blockIdx.x * 32, r0 = blockIdx.y * 32;
    const int tx = threadIdx.x, ty = threadIdx.y;
#pragma unroll
    for (int i = ty; i < 32; i += 8) {
        float v = in[zi + (long)(r0 + i) * C + c0 + tx];
        t[i][tx] = v;
        lin[zi + (long)(r0 + i) * C + c0 + tx] = (uint8_t)__nv_cvt_float_to_fp8(v, __NV_SATFINITE, __NV_E4M3);
    }
    __syncthreads();
#pragma unroll
    for (int i = ty; i < 32; i += 8)
        tr[zo + (long)(c0 + i) * R + r0 + tx] = __float2half(t[tx][i]);
}

// ---------------- f32 transpose -> f16 ----------------
__global__ __launch_bounds__(256)
void transp_k(const float* __restrict__ in, __half* __restrict__ out, int R, int C)
{
    __shared__ float t[32][33];
    const int c0 = blockIdx.x * 32, r0 = blockIdx.y * 32;
    const int tx = threadIdx.x, ty = threadIdx.y;
#pragma unroll
    for (int i = ty; i < 32; i += 8)
        t[i][tx] = in[(long)(r0 + i) * C + c0 + tx];
    __syncthreads();
#pragma unroll
    for (int i = ty; i < 32; i += 8)
        out[(long)(c0 + i) * R + r0 + tx] = __float2half(t[tx][i]);
}

// ---------------- f32 transpose -> fp8 ----------------
__global__ __launch_bounds__(256)
void transp8_k(const float* __restrict__ in, uint8_t* __restrict__ out, int R, int C)
{
    __shared__ float t[32][33];
    const int c0 = blockIdx.x * 32, r0 = blockIdx.y * 32;
    const int tx = threadIdx.x, ty = threadIdx.y;
#pragma unroll
    for (int i = ty; i < 32; i += 8)
        t[i][tx] = in[(long)(r0 + i) * C + c0 + tx];
    __syncthreads();
#pragma unroll
    for (int i = ty; i < 32; i += 8)
        out[(long)(c0 + i) * R + r0 + tx] = (uint8_t)__nv_cvt_float_to_fp8(t[tx][i], __NV_SATFINITE, __NV_E4M3);
}

// ---------------- LayerNorm: fp32 in -> f16 out ----------------
__global__ __launch_bounds__(256)
void ln_k(const float* __restrict__ in, __half* __restrict__ out,
          const float* __restrict__ gamma, const float* __restrict__ beta)
{
    __shared__ float sh[8];
    const long row = blockIdx.x;
    const float* p = in + row * CH;
    const int tid = threadIdx.x, lane = tid & 31, w = tid >> 5;
    const int c = tid * 4;

    float4 xv = *(const float4*)(p + c);
    float s = xv.x + xv.y + xv.z + xv.w;
#pragma unroll
    for (int o = 16; o; o >>= 1) s += __shfl_xor_sync(0xffffffffu, s, o);
    if (lane == 0) sh[w] = s;
    __syncthreads();
    float tot = 0.f;
#pragma unroll
    for (int i = 0; i < 8; i++) tot += sh[i];
    const float mu = tot * (1.f / CH);

    float d0 = xv.x - mu, d1 = xv.y - mu, d2 = xv.z - mu, d3 = xv.w - mu;
    float q = d0 * d0 + d1 * d1 + d2 * d2 + d3 * d3;
#pragma unroll
    for (int o = 16; o; o >>= 1) q += __shfl_xor_sync(0xffffffffu, q, o);
    __syncthreads();
    if (lane == 0) sh[w] = q;
    __syncthreads();
    float vtot = 0.f;
#pragma unroll
    for (int i = 0; i < 8; i++) vtot += sh[i];
    const float rstd = rsqrtf(vtot * (1.f / CH) + 1e-6f);

    float4 g  = *(const float4*)(gamma + c);
    float4 be = *(const float4*)(beta + c);
    __half2* o2 = (__half2*)(out + row * CH + c);
    o2[0] = __floats2half2_rn(d0 * rstd * g.x + be.x, d1 * rstd * g.y + be.y);
    o2[1] = __floats2half2_rn(d2 * rstd * g.z + be.z, d3 * rstd * g.w + be.w);
}

// ---------------- launch ----------------
extern "C" void kernel_launch(void* const* d_in, const int* in_sizes, int n_in,
                              void* d_out, int out_size)
{
    const float* Q     = (const float*)d_in[0];
    const float* Kk    = (const float*)d_in[1];
    const float* kmask = (const float*)d_in[2];
    const float* qmask = (const float*)d_in[3];
    const float* u     = (const float*)d_in[4];
    const float* dd    = (const float*)d_in[5];
    const float* W1    = (const float*)d_in[6];
    const float* b1    = (const float*)d_in[7];
    const float* W2    = (const float*)d_in[8];
    const float* b2    = (const float*)d_in[9];
    const float* gamma = (const float*)d_in[10];
    const float* beta  = (const float*)d_in[11];

    uint8_t *hQ8, *hK8, *uT8, *f1q, *f2q;
    __half  *hKT, *hW1T, *hW2T, *hS, *hLN, *hH;
    float   *ctx, *part, *invs;
    cudaGetSymbolAddress((void**)&hQ8, g_hQ8);
    cudaGetSymbolAddress((void**)&hK8, g_hK8);
    cudaGetSymbolAddress((void**)&uT8, g_uT8);
    cudaGetSymbolAddress((void**)&f1q, g_f1q);
    cudaGetSymbolAddress((void**)&f2q, g_f2q);
    cudaGetSymbolAddress((void**)&hKT, g_hKT);
    cudaGetSymbolAddress((void**)&hW1T, g_hW1T);
    cudaGetSymbolAddress((void**)&hW2T, g_hW2T);
    cudaGetSymbolAddress((void**)&hS,  g_hS);
    cudaGetSymbolAddress((void**)&hLN, g_hLN);
    cudaGetSymbolAddress((void**)&hH,  g_hH);
    cudaGetSymbolAddress((void**)&ctx, g_ctx);
    cudaGetSymbolAddress((void**)&part, g_part);
    cudaGetSymbolAddress((void**)&invs, g_invs);

    const long TC  = (long)TT * CH;
    const long TTl = (long)TT * TT;

    float* out2 = (float*)d_out;
    float* outq = (float*)d_out;
    if ((long)out_size >= 2 * (long)NTC) out2 = (float*)d_out + NTC;

    cudaFuncSetAttribute(gemm8<EPI_PROJ>,             cudaFuncAttributeMaxDynamicSharedMemorySize, SMEM_G);
    cudaFuncSetAttribute(gemm8<EPI_EXP>,              cudaFuncAttributeMaxDynamicSharedMemorySize, SMEM_G);
    cudaFuncSetAttribute(gemmv5<EPI_CTX, false>,      cudaFuncAttributeMaxDynamicSharedMemorySize, SMEM_G);
    cudaFuncSetAttribute(gemmv5<EPI_BIAS_RELU, true>, cudaFuncAttributeMaxDynamicSharedMemorySize, SMEM_G);
    cudaFuncSetAttribute(gemmv5<EPI_BIAS, false>,     cudaFuncAttributeMaxDynamicSharedMemorySize, SMEM_G);

    // ---- conversions (6th launch = proj GEMM, for ncu -s 5) ----
    convq_k<<<NTC / 1024, 256>>>(Q, hQ8, outq);                                  // 1
    transp8_k<<<dim3(CH / 32, CH / 32), dim3(32, 8)>>>(u,  uT8,  CH, CH);        // 2
    transp_k<<<dim3(CH / 32, CH / 32), dim3(32, 8)>>>(W1, hW1T, CH, CH);         // 3
    transp_k<<<dim3(CH / 32, CH / 32), dim3(32, 8)>>>(W2, hW2T, CH, CH);         // 4
    convkt_k<<<dim3(CH / 32, TT / 32, BB), dim3(32, 8)>>>(Kk, hK8, hKT, TT, CH, TC, TC); // 5

    // ---- 1+2) f1 = relu(Q@u)*d ; f2 = relu(K@u)   fp8 in/out, grid.z=2 ----       6
    gemm8<EPI_PROJ><<<dim3(CH / BN, BB * TT / BM, 2), NTHR, SMEM_G>>>(
        hQ8, hK8, uT8, f1q, f2q, BB * TT, CH, CH, 0, 0, 0, dd, 0, 0.f, nullptr);

    // ---- 3) expS = exp((f1 @ f2^T)/32) masked -> f16, + row partial sums ----
    gemm8<EPI_EXP><<<dim3(TT / BN, TT / BM, BB), NTHR, SMEM_G>>>(
        f1q, nullptr, f2q, hS, nullptr, TT, TT, CH, TC, TC, TTl, kmask, TT,
        1.0f / 32.0f, part);

    // ---- 4) invs = qmask / rowsum ----
    invs_k<<<BB * TT / 256, 256>>>(part, qmask, invs);

    // ---- 5) ctx = (expS @ K) * invs[row] + Q  (f16 GEMM, fp32 out) ----
    gemmv5<EPI_CTX, false><<<dim3(CH / BN, TT / BM, BB), NTHR, SMEM_G>>>(
        hS, hKT, ctx, TT, CH, TT, TTl, TC, TC, invs, TT, Q, TC, 0.f);

    // ---- 6) LayerNorm -> f16 ----
    ln_k<<<BB * TT, 256>>>(ctx, hLN, gamma, beta);

    // ---- 7) h = relu(LN @ W1 + b1) -> f16 ----
    gemmv5<EPI_BIAS_RELU, true><<<dim3(CH / BN, BB * TT / BM, 1), NTHR, SMEM_G>>>(
        hLN, hW1T, hH, BB * TT, CH, CH, 0, 0, 0, b1, 0, nullptr, 0, 0.f);

    // ---- 8) out2 = h @ W2 + b2 (fp32 out) ----
    gemmv5<EPI_BIAS, false><<<dim3(CH / BN, BB * TT / BM, 1), NTHR, SMEM_G>>>(
        hH, hW2T, out2, BB * TT, CH, CH, 0, 0, 0, b2, 0, nullptr, 0, 0.f);
}

// round 9
// speedup vs baseline: 1.0006x; 1.0006x over previous
#include <cuda_runtime.h>
#include <cuda_fp16.h>
#include <math.h>
#include <stdint.h>

#define BB  8
#define TT  2048
#define CH  1024

#define NTC   (BB * TT * CH)              // 16,777,216
#define NTT   ((size_t)BB * TT * TT)      // 33,554,432

// ---------------- scratch (no allocations allowed) ----------------
__device__ __half g_hQ [NTC];
__device__ __half g_hK [NTC];
__device__ __half g_hKT[NTC];             // per-batch [CH][TT]
__device__ __half g_hUT [CH * CH];
__device__ __half g_hW1T[CH * CH];
__device__ __half g_hW2T[CH * CH];
__device__ __half g_f1h[NTC];
__device__ __half g_f2h[NTC];
__device__ __half g_hS [NTT];             // f16 exp(scores)
__device__ float  g_part[BB * TT * 8];
__device__ float  g_invs[BB * TT];
__device__ float  g_ctx[NTC];
__device__ __half g_hLN[NTC];
__device__ __half g_hH [NTC];

enum { EPI_PROJ = 0, EPI_CTX, EPI_BIAS_RELU, EPI_BIAS };

// ---------------- PTX helpers ----------------
__device__ __forceinline__ uint32_t smem_u32(const void* p) {
    uint32_t a;
    asm("{ .reg .u64 t; cvta.to.shared.u64 t, %1; cvt.u32.u64 %0, t; }" : "=r"(a) : "l"(p));
    return a;
}
__device__ __forceinline__ void ldsm4(uint32_t* r, uint32_t addr) {
    asm volatile("ldmatrix.sync.aligned.m8n8.x4.shared.b16 {%0,%1,%2,%3}, [%4];"
        : "=r"(r[0]), "=r"(r[1]), "=r"(r[2]), "=r"(r[3]) : "r"(addr));
}
__device__ __forceinline__ void mma_f16(float* d, const uint32_t* a, const uint32_t* b) {
    asm volatile(
        "mma.sync.aligned.m16n8k16.row.col.f32.f16.f16.f32 "
        "{%0,%1,%2,%3}, {%4,%5,%6,%7}, {%8,%9}, {%0,%1,%2,%3};"
        : "+f"(d[0]), "+f"(d[1]), "+f"(d[2]), "+f"(d[3])
        : "r"(a[0]), "r"(a[1]), "r"(a[2]), "r"(a[3]), "r"(b[0]), "r"(b[1]));
}
// f16 accumulator variant (2 packed regs)
__device__ __forceinline__ void mma_h16(uint32_t* d, const uint32_t* a, const uint32_t* b) {
    asm volatile(
        "mma.sync.aligned.m16n8k16.row.col.f16.f16.f16.f16 "
        "{%0,%1}, {%2,%3,%4,%5}, {%6,%7}, {%0,%1};"
        : "+r"(d[0]), "+r"(d[1])
        : "r"(a[0]), "r"(a[1]), "r"(a[2]), "r"(a[3]), "r"(b[0]), "r"(b[1]));
}
#define CP16(dst, src) \
    asm volatile("cp.async.cg.shared.global [%0], [%1], 16;" :: "r"(dst), "l"(src) : "memory")
#define CP_COMMIT()  asm volatile("cp.async.commit_group;" ::: "memory")
#define CP_WAIT1()   asm volatile("cp.async.wait_group 1;" ::: "memory")
#define CP_WAIT0()   asm volatile("cp.async.wait_group 0;" ::: "memory")

// swizzled offset within a tile: rows of 64B (32 halves), 16B column c (0..3)
__device__ __forceinline__ uint32_t swz(int row, int c) {
    return (uint32_t)(row * 64 + (((c) ^ ((row >> 1) & 3)) << 4));
}

// CTA tile 128x256, K-tile 32, 3-stage cp.async ring, 16 warps (4m x 4n) of 32x64.
#define BM 128
#define BN 256
#define A_BYTES (BM * 64)                 // 8192
#define B_BYTES (BN * 64)                 // 16384
#define STG     (A_BYTES + B_BYTES)       // 24576
#define SMEM_G  (3 * STG)                 // 73728
#define NTHR    512

// common prologue/mainloop pieces shared by both kernels via macros
#define GEMM_SETUP()                                                           \
    extern __shared__ char smem[];                                             \
    const uint32_t sb = smem_u32(smem);                                        \
    const int tid = threadIdx.x, lane = tid & 31, warp = tid >> 5;             \
    const int wm = warp >> 2, wn = warp & 3;                                   \
    const int z = blockIdx.z;                                                  \
    uint32_t adst, bdst[2];                                                    \
    const __half* asrc;                                                        \
    const __half* bsrc[2];                                                     \
    {                                                                          \
        int r = tid >> 2, c = tid & 3;                                         \
        adst = swz(r, c);                                                      \
        asrc = Ap + (long)r * K + c * 8;                                       \
    }                                                                          \
    _Pragma("unroll")                                                          \
    for (int i = 0; i < 2; i++) {                                              \
        int q = tid + i * NTHR, r = q >> 2, c = q & 3;                         \
        bdst[i] = A_BYTES + swz(r, c);                                         \
        bsrc[i] = Bp + (long)r * K + c * 8;                                    \
    }                                                                          \
    const int q8 = lane >> 3, rr = lane & 7;                                   \
    const int rA = wm * 32 + (q8 & 1) * 8 + rr;                                \
    const int xA = (rA >> 1) & 3;                                              \
    const int cA = q8 >> 1;                                                    \
    const int rB = wn * 64 + (q8 >> 1) * 8 + rr;                               \
    const int xB = (rB >> 1) & 3;                                              \
    const int cB = q8 & 1;

#define ISSUE(kt)                                                              \
    do {                                                                       \
        const uint32_t _s = sb + ((kt) % 3) * STG;                             \
        const long _ko = (long)(kt) * 32;                                      \
        CP16(_s + adst, asrc + _ko);                                           \
        CP16(_s + bdst[0], bsrc[0] + _ko);                                     \
        CP16(_s + bdst[1], bsrc[1] + _ko);                                     \
        CP_COMMIT();                                                           \
    } while (0)

// ---------------- f16-in / f32-acc GEMM ----------------
template <int EPI, bool OUTH>
__global__ void __launch_bounds__(NTHR, 1)
gemmv5(const __half* __restrict__ A, const __half* __restrict__ A2,
       const __half* __restrict__ B, void* __restrict__ Cv, void* __restrict__ Cv2,
       int M, int N, int K, long sA, long sB, long sC,
       const float* __restrict__ vec, long sVec,
       const float* __restrict__ add, long sAdd)
{
    const __half* Abase = A;
    void* Cbase = Cv;
    if (EPI == EPI_PROJ && blockIdx.z == 1) { Abase = A2; Cbase = Cv2; }
    const __half* Ap = Abase + (long)blockIdx.z * sA + (long)(blockIdx.y * BM) * K;
    const __half* Bp = B + (long)blockIdx.z * sB + (long)(blockIdx.x * BN) * K;

    GEMM_SETUP();

    float acc[2][8][4];
#pragma unroll
    for (int mi = 0; mi < 2; mi++)
#pragma unroll
        for (int ni = 0; ni < 8; ni++)
#pragma unroll
            for (int e = 0; e < 4; e++) acc[mi][ni][e] = 0.f;

    ISSUE(0);
    ISSUE(1);

    const int nCh = K / 32;
    for (int kt = 0; kt < nCh; kt++) {
        if (kt + 1 < nCh) CP_WAIT1(); else CP_WAIT0();
        __syncthreads();
        const uint32_t sbase = sb + (kt % 3) * STG;
#pragma unroll
        for (int s = 0; s < 2; s++) {
            uint32_t af[2][4];
#pragma unroll
            for (int mi = 0; mi < 2; mi++)
                ldsm4(af[mi], sbase + (uint32_t)((rA + mi * 16) * 64) +
                              (uint32_t)((((2 * s + cA) ^ xA)) << 4));
#pragma unroll
            for (int nip = 0; nip < 4; nip++) {
                uint32_t t4[4];
                ldsm4(t4, sbase + A_BYTES + (uint32_t)((rB + nip * 16) * 64) +
                          (uint32_t)((((2 * s + cB) ^ xB)) << 4));
#pragma unroll
                for (int mi = 0; mi < 2; mi++) mma_f16(acc[mi][2 * nip],     af[mi], &t4[0]);
#pragma unroll
                for (int mi = 0; mi < 2; mi++) mma_f16(acc[mi][2 * nip + 1], af[mi], &t4[2]);
            }
        }
        if (kt + 2 < nCh) ISSUE(kt + 2);
    }

    const float* vv = vec ? vec + (long)z * sVec : nullptr;
    const float* adb = add ? add + (long)z * sAdd : nullptr;
    const long cBase = (long)z * sC;

#pragma unroll
    for (int mi = 0; mi < 2; mi++) {
        const int r0 = blockIdx.y * BM + wm * 32 + mi * 16 + (lane >> 2);
        float rowS[2];
        if (EPI == EPI_CTX) { rowS[0] = vv[r0]; rowS[1] = vv[r0 + 8]; }
#pragma unroll
        for (int ni = 0; ni < 8; ni++) {
            const int c = blockIdx.x * BN + wn * 64 + ni * 8 + (lane & 3) * 2;
#pragma unroll
            for (int p = 0; p < 2; p++) {
                const int r = r0 + p * 8;
                float v0 = acc[mi][ni][p * 2 + 0];
                float v1 = acc[mi][ni][p * 2 + 1];
                if (EPI == EPI_PROJ) {
                    v0 = fmaxf(v0, 0.f); v1 = fmaxf(v1, 0.f);
                    if (z == 0) { v0 *= vv[c]; v1 *= vv[c + 1]; }
                }
                if (EPI == EPI_CTX) {
                    float2 a2 = *(const float2*)(adb + (long)r * N + c);
                    v0 = v0 * rowS[p] + a2.x;
                    v1 = v1 * rowS[p] + a2.y;
                }
                if (EPI == EPI_BIAS_RELU) { v0 = fmaxf(v0 + vv[c], 0.f); v1 = fmaxf(v1 + vv[c + 1], 0.f); }
                if (EPI == EPI_BIAS)      { v0 += vv[c]; v1 += vv[c + 1]; }
                if (OUTH) {
                    __half* op = (__half*)Cbase + cBase + (long)r * N + c;
                    *(__half2*)op = __floats2half2_rn(v0, v1);
                } else {
                    float* op = (float*)Cbase + cBase + (long)r * N + c;
                    *(float2*)op = make_float2(v0, v1);
                }
            }
        }
    }
}

// ---------------- f16-in / f16-acc GEMM, EXP epilogue (score GEMM) ----------------
__global__ void __launch_bounds__(NTHR, 1)
gemme(const __half* __restrict__ A, const __half* __restrict__ B,
      __half* __restrict__ Cv,
      int M, int N, int K, long sA, long sB, long sC,
      const float* __restrict__ kmask, long sVec, float scale,
      float* __restrict__ part)
{
    const __half* Ap = A + (long)blockIdx.z * sA + (long)(blockIdx.y * BM) * K;
    const __half* Bp = B + (long)blockIdx.z * sB + (long)(blockIdx.x * BN) * K;

    GEMM_SETUP();

    uint32_t acc[2][8][2];
#pragma unroll
    for (int mi = 0; mi < 2; mi++)
#pragma unroll
        for (int ni = 0; ni < 8; ni++) { acc[mi][ni][0] = 0u; acc[mi][ni][1] = 0u; }

    ISSUE(0);
    ISSUE(1);

    const int nCh = K / 32;
    for (int kt = 0; kt < nCh; kt++) {
        if (kt + 1 < nCh) CP_WAIT1(); else CP_WAIT0();
        __syncthreads();
        const uint32_t sbase = sb + (kt % 3) * STG;
#pragma unroll
        for (int s = 0; s < 2; s++) {
            uint32_t af[2][4];
#pragma unroll
            for (int mi = 0; mi < 2; mi++)
                ldsm4(af[mi], sbase + (uint32_t)((rA + mi * 16) * 64) +
                              (uint32_t)((((2 * s + cA) ^ xA)) << 4));
#pragma unroll
            for (int nip = 0; nip < 4; nip++) {
                uint32_t t4[4];
                ldsm4(t4, sbase + A_BYTES + (uint32_t)((rB + nip * 16) * 64) +
                          (uint32_t)((((2 * s + cB) ^ xB)) << 4));
#pragma unroll
                for (int mi = 0; mi < 2; mi++) mma_h16(acc[mi][2 * nip],     af[mi], &t4[0]);
#pragma unroll
                for (int mi = 0; mi < 2; mi++) mma_h16(acc[mi][2 * nip + 1], af[mi], &t4[2]);
            }
        }
        if (kt + 2 < nCh) ISSUE(kt + 2);
    }

    const float* vv = kmask + (long)z * sVec;
    const long cBase = (long)z * sC;

    float rsl[2][2] = {{0.f, 0.f}, {0.f, 0.f}};
#pragma unroll
    for (int mi = 0; mi < 2; mi++) {
        const int r0 = blockIdx.y * BM + wm * 32 + mi * 16 + (lane >> 2);
#pragma unroll
        for (int ni = 0; ni < 8; ni++) {
            const int c = blockIdx.x * BN + wn * 64 + ni * 8 + (lane & 3) * 2;
            const float m0 = vv[c], m1 = vv[c + 1];
#pragma unroll
            for (int p = 0; p < 2; p++) {
                const int r = r0 + p * 8;
                float2 sv = __half22float2(*(const __half2*)&acc[mi][ni][p]);
                float e0 = (m0 == 0.f) ? 0.f : expf(sv.x * scale);
                float e1 = (m1 == 0.f) ? 0.f : expf(sv.y * scale);
                __half2 h = __floats2half2_rn(e0, e1);
                *(__half2*)(Cv + cBase + (long)r * N + c) = h;
                float2 fr = __half22float2(h);
                rsl[mi][p] += fr.x + fr.y;
            }
        }
    }
    float* rsf = (float*)(smem + (nCh % 3) * STG);
#pragma unroll
    for (int mi = 0; mi < 2; mi++)
#pragma unroll
        for (int p = 0; p < 2; p++) {
            float s = rsl[mi][p];
            s += __shfl_xor_sync(0xffffffffu, s, 1);
            s += __shfl_xor_sync(0xffffffffu, s, 2);
            if ((lane & 3) == 0)
                rsf[(wm * 32 + mi * 16 + p * 8 + (lane >> 2)) * 4 + wn] = s;
        }
    __syncthreads();
    if (tid < BM) {
        float s = rsf[tid * 4] + rsf[tid * 4 + 1] + rsf[tid * 4 + 2] + rsf[tid * 4 + 3];
        part[((long)z * TT + blockIdx.y * BM + tid) * 8 + blockIdx.x] = s;
    }
}

// ---------------- invs: qmask/rowsum ----------------
__global__ __launch_bounds__(256)
void invs_k(const float* __restrict__ part, const float* __restrict__ qmask,
            float* __restrict__ invs)
{
    const int i = blockIdx.x * 256 + threadIdx.x;
    float s = 0.f;
#pragma unroll
    for (int j = 0; j < 8; j++) s += part[(long)i * 8 + j];
    invs[i] = qmask[i] / s;
}

// ---------------- Q convert: f32 -> f16, plus fp32 copy to output ----------------
__global__ __launch_bounds__(256)
void convq_k(const float* __restrict__ in, __half* __restrict__ out, float* __restrict__ outc)
{
    const int i = blockIdx.x * 256 + threadIdx.x;
    float4 v = ((const float4*)in)[i];
    __half2* o = (__half2*)out + (long)i * 2;
    o[0] = __floats2half2_rn(v.x, v.y);
    o[1] = __floats2half2_rn(v.z, v.w);
    ((float4*)outc)[i] = v;
}

// ---------------- K convert + transpose: f32 [R][C] -> f16 linear + f16 [C][R] ----------------
__global__ __launch_bounds__(256)
void convkt_k(const float* __restrict__ in, __half* __restrict__ lin, __half* __restrict__ tr,
              int R, int C, long sIn, long sOut)
{
    __shared__ float t[32][33];
    const long zi = (long)blockIdx.z * sIn, zo = (long)blockIdx.z * sOut;
    const int c0 = blockIdx.x * 32, r0 = blockIdx.y * 32;
    const int tx = threadIdx.x, ty = threadIdx.y;
#pragma unroll
    for (int i = ty; i < 32; i += 8) {
        float v = in[zi + (long)(r0 + i) * C + c0 + tx];
        t[i][tx] = v;
        lin[zi + (long)(r0 + i) * C + c0 + tx] = __float2half(v);
    }
    __syncthreads();
#pragma unroll
    for (int i = ty; i < 32; i += 8)
        tr[zo + (long)(c0 + i) * R + r0 + tx] = __float2half(t[tx][i]);
}

// ---------------- batched square transpose f32 -> f16: three matrices ----------------
__global__ __launch_bounds__(256)
void transp3_k(const float* __restrict__ s0, const float* __restrict__ s1,
               const float* __restrict__ s2,
               __half* __restrict__ d0, __half* __restrict__ d1, __half* __restrict__ d2)
{
    __shared__ float t[32][33];
    const float* in  = blockIdx.z == 0 ? s0 : (blockIdx.z == 1 ? s1 : s2);
    __half* out      = blockIdx.z == 0 ? d0 : (blockIdx.z == 1 ? d1 : d2);
    const int c0 = blockIdx.x * 32, r0 = blockIdx.y * 32;
    const int tx = threadIdx.x, ty = threadIdx.y;
#pragma unroll
    for (int i = ty; i < 32; i += 8)
        t[i][tx] = in[(long)(r0 + i) * CH + c0 + tx];
    __syncthreads();
#pragma unroll
    for (int i = ty; i < 32; i += 8)
        out[(long)(c0 + i) * CH + r0 + tx] = __float2half(t[tx][i]);
}

// ---------------- LayerNorm: fp32 in -> f16 out ----------------
__global__ __launch_bounds__(256)
void ln_k(const float* __restrict__ in, __half* __restrict__ out,
          const float* __restrict__ gamma, const float* __restrict__ beta)
{
    __shared__ float sh[8];
    const long row = blockIdx.x;
    const float* p = in + row * CH;
    const int tid = threadIdx.x, lane = tid & 31, w = tid >> 5;
    const int c = tid * 4;

    float4 xv = *(const float4*)(p + c);
    float s = xv.x + xv.y + xv.z + xv.w;
#pragma unroll
    for (int o = 16; o; o >>= 1) s += __shfl_xor_sync(0xffffffffu, s, o);
    if (lane == 0) sh[w] = s;
    __syncthreads();
    float tot = 0.f;
#pragma unroll
    for (int i = 0; i < 8; i++) tot += sh[i];
    const float mu = tot * (1.f / CH);

    float d0 = xv.x - mu, d1 = xv.y - mu, d2 = xv.z - mu, d3 = xv.w - mu;
    float q = d0 * d0 + d1 * d1 + d2 * d2 + d3 * d3;
#pragma unroll
    for (int o = 16; o; o >>= 1) q += __shfl_xor_sync(0xffffffffu, q, o);
    __syncthreads();
    if (lane == 0) sh[w] = q;
    __syncthreads();
    float vtot = 0.f;
#pragma unroll
    for (int i = 0; i < 8; i++) vtot += sh[i];
    const float rstd = rsqrtf(vtot * (1.f / CH) + 1e-6f);

    float4 g  = *(const float4*)(gamma + c);
    float4 be = *(const float4*)(beta + c);
    __half2* o2 = (__half2*)(out + row * CH + c);
    o2[0] = __floats2half2_rn(d0 * rstd * g.x + be.x, d1 * rstd * g.y + be.y);
    o2[1] = __floats2half2_rn(d2 * rstd * g.z + be.z, d3 * rstd * g.w + be.w);
}

// ---------------- launch ----------------
extern "C" void kernel_launch(void* const* d_in, const int* in_sizes, int n_in,
                              void* d_out, int out_size)
{
    const float* Q     = (const float*)d_in[0];
    const float* Kk    = (const float*)d_in[1];
    const float* kmask = (const float*)d_in[2];
    const float* qmask = (const float*)d_in[3];
    const float* u     = (const float*)d_in[4];
    const float* dd    = (const float*)d_in[5];
    const float* W1    = (const float*)d_in[6];
    const float* b1    = (const float*)d_in[7];
    const float* W2    = (const float*)d_in[8];
    const float* b2    = (const float*)d_in[9];
    const float* gamma = (const float*)d_in[10];
    const float* beta  = (const float*)d_in[11];

    __half *hQ, *hK, *hKT, *hUT, *hW1T, *hW2T, *f1h, *f2h, *hS, *hLN, *hH;
    float  *ctx, *part, *invs;
    cudaGetSymbolAddress((void**)&hQ,  g_hQ);
    cudaGetSymbolAddress((void**)&hK,  g_hK);
    cudaGetSymbolAddress((void**)&hKT, g_hKT);
    cudaGetSymbolAddress((void**)&hUT, g_hUT);
    cudaGetSymbolAddress((void**)&hW1T, g_hW1T);
    cudaGetSymbolAddress((void**)&hW2T, g_hW2T);
    cudaGetSymbolAddress((void**)&f1h, g_f1h);
    cudaGetSymbolAddress((void**)&f2h, g_f2h);
    cudaGetSymbolAddress((void**)&hS,  g_hS);
    cudaGetSymbolAddress((void**)&ctx, g_ctx);
    cudaGetSymbolAddress((void**)&hLN, g_hLN);
    cudaGetSymbolAddress((void**)&hH,  g_hH);
    cudaGetSymbolAddress((void**)&part, g_part);
    cudaGetSymbolAddress((void**)&invs, g_invs);

    const long TC  = (long)TT * CH;
    const long TTl = (long)TT * TT;

    float* out2 = (float*)d_out;
    float* outq = (float*)d_out;
    if ((long)out_size >= 2 * (long)NTC) out2 = (float*)d_out + NTC;

    cudaFuncSetAttribute(gemmv5<EPI_PROJ, true>,      cudaFuncAttributeMaxDynamicSharedMemorySize, SMEM_G);
    cudaFuncSetAttribute(gemme,                       cudaFuncAttributeMaxDynamicSharedMemorySize, SMEM_G);
    cudaFuncSetAttribute(gemmv5<EPI_CTX, false>,      cudaFuncAttributeMaxDynamicSharedMemorySize, SMEM_G);
    cudaFuncSetAttribute(gemmv5<EPI_BIAS_RELU, true>, cudaFuncAttributeMaxDynamicSharedMemorySize, SMEM_G);
    cudaFuncSetAttribute(gemmv5<EPI_BIAS, false>,     cudaFuncAttributeMaxDynamicSharedMemorySize, SMEM_G);

    // ---- conversions ----
    convq_k<<<NTC / 1024, 256>>>(Q, hQ, outq);                                        // 1
    convkt_k<<<dim3(CH / 32, TT / 32, BB), dim3(32, 8)>>>(Kk, hK, hKT, TT, CH, TC, TC); // 2
    transp3_k<<<dim3(CH / 32, CH / 32, 3), dim3(32, 8)>>>(u, W1, W2, hUT, hW1T, hW2T);  // 3

    // ---- 1+2) f1 = relu(Q@u)*d ; f2 = relu(K@u)  (merged, grid.z=2) ----             4
    gemmv5<EPI_PROJ, true><<<dim3(CH / BN, BB * TT / BM, 2), NTHR, SMEM_G>>>(
        hQ, hK, hUT, f1h, f2h, BB * TT, CH, CH, 0, 0, 0, dd, 0, nullptr, 0);

    // ---- 3) expS = exp((f1 @ f2^T)/32) masked -> f16, + row partial sums (f16 acc) ----
    gemme<<<dim3(TT / BN, TT / BM, BB), NTHR, SMEM_G>>>(
        f1h, f2h, hS, TT, TT, CH, TC, TC, TTl, kmask, TT, 1.0f / 32.0f, part);

    // ---- 4) invs = qmask / rowsum ----
    invs_k<<<BB * TT / 256, 256>>>(part, qmask, invs);

    // ---- 5) ctx = (expS @ K) * invs[row] + Q  (fp32 out) ----
    gemmv5<EPI_CTX, false><<<dim3(CH / BN, TT / BM, BB), NTHR, SMEM_G>>>(
        hS, nullptr, hKT, ctx, nullptr, TT, CH, TT, TTl, TC, TC, invs, TT, Q, TC);

    // ---- 6) LayerNorm -> f16 ----
    ln_k<<<BB * TT, 256>>>(ctx, hLN, gamma, beta);

    // ---- 7) h = relu(LN @ W1 + b1) -> f16 ----
    gemmv5<EPI_BIAS_RELU, true><<<dim3(CH / BN, BB * TT / BM, 1), NTHR, SMEM_G>>>(
        hLN, nullptr, hW1T, hH, nullptr, BB * TT, CH, CH, 0, 0, 0, b1, 0, nullptr, 0);

    // ---- 8) out2 = h @ W2 + b2 (fp32 out) ----
    gemmv5<EPI_BIAS, false><<<dim3(CH / BN, BB * TT / BM, 1), NTHR, SMEM_G>>>(
        hH, nullptr, hW2T, out2, nullptr, BB * TT, CH, CH, 0, 0, 0, b2, 0, nullptr, 0);
}

// round 10
// speedup vs baseline: 1.1646x; 1.1638x over previous
#include <cuda_runtime.h>
#include <cuda_fp16.h>
#include <math.h>
#include <stdint.h>

#define BB  8
#define TT  2048
#define CH  1024

#define NTC   (BB * TT * CH)              // 16,777,216
#define NTT   ((size_t)BB * TT * TT)      // 33,554,432

// ---------------- scratch (no allocations allowed) ----------------
__device__ __half g_hQ [NTC];
__device__ __half g_hK [NTC];
__device__ __half g_hKT[NTC];             // per-batch [CH][TT]
__device__ __half g_hUT [CH * CH];
__device__ __half g_hW1T[CH * CH];
__device__ __half g_hW2T[CH * CH];
__device__ __half g_f1h[NTC];
__device__ __half g_f2h[NTC];
__device__ __half g_hS [NTT];             // f16 exp(scores)
__device__ float  g_part[BB * TT * 16];
__device__ float  g_invs[BB * TT];
__device__ float  g_ctx[NTC];
__device__ __half g_hLN[NTC];
__device__ __half g_hH [NTC];

enum { EPI_PROJ = 0, EPI_EXP, EPI_CTX, EPI_BIAS_RELU, EPI_BIAS };

// ---------------- PTX helpers ----------------
__device__ __forceinline__ uint32_t smem_u32(const void* p) {
    uint32_t a;
    asm("{ .reg .u64 t; cvta.to.shared.u64 t, %1; cvt.u32.u64 %0, t; }" : "=r"(a) : "l"(p));
    return a;
}
__device__ __forceinline__ void ldsm4(uint32_t* r, uint32_t addr) {
    asm volatile("ldmatrix.sync.aligned.m8n8.x4.shared.b16 {%0,%1,%2,%3}, [%4];"
        : "=r"(r[0]), "=r"(r[1]), "=r"(r[2]), "=r"(r[3]) : "r"(addr));
}
__device__ __forceinline__ void mma_f16(float* d, const uint32_t* a, const uint32_t* b) {
    asm volatile(
        "mma.sync.aligned.m16n8k16.row.col.f32.f16.f16.f32 "
        "{%0,%1,%2,%3}, {%4,%5,%6,%7}, {%8,%9}, {%0,%1,%2,%3};"
        : "+f"(d[0]), "+f"(d[1]), "+f"(d[2]), "+f"(d[3])
        : "r"(a[0]), "r"(a[1]), "r"(a[2]), "r"(a[3]), "r"(b[0]), "r"(b[1]));
}
#define CP16(dst, src) \
    asm volatile("cp.async.cg.shared.global [%0], [%1], 16;" :: "r"(dst), "l"(src) : "memory")
#define CP_COMMIT()  asm volatile("cp.async.commit_group;" ::: "memory")
#define CP_WAIT1()   asm volatile("cp.async.wait_group 1;" ::: "memory")
#define CP_WAIT0()   asm volatile("cp.async.wait_group 0;" ::: "memory")

// swizzled offset within a tile: rows of 64B (32 halves), 16B column c (0..3)
__device__ __forceinline__ uint32_t swz(int row, int c) {
    return (uint32_t)(row * 64 + (((c) ^ ((row >> 1) & 3)) << 4));
}

// CTA tile 128x128, K-tile 32, 3-stage cp.async ring, 8 warps (4m x 2n) of 32x64.
// 256 threads, 2 CTAs/SM -> two independent barrier domains per SM.
#define BM 128
#define BN 128
#define A_BYTES (BM * 64)                 // 8192
#define B_BYTES (BN * 64)                 // 8192
#define STG     (A_BYTES + B_BYTES)       // 16384
#define SMEM_G  (3 * STG)                 // 49152
#define NTHR    256

#define GEMM_SETUP()                                                           \
    extern __shared__ char smem[];                                             \
    const uint32_t sb = smem_u32(smem);                                        \
    const int tid = threadIdx.x, lane = tid & 31, warp = tid >> 5;             \
    const int wm = warp >> 1, wn = warp & 1;                                   \
    const int z = blockIdx.z;                                                  \
    uint32_t adst[2], bdst[2];                                                 \
    const __half* asrc[2];                                                     \
    const __half* bsrc[2];                                                     \
    _Pragma("unroll")                                                          \
    for (int i = 0; i < 2; i++) {                                              \
        int q = tid + i * NTHR, r = q >> 2, c = q & 3;                         \
        adst[i] = swz(r, c);                                                   \
        asrc[i] = Ap + (long)r * K + c * 8;                                    \
        bdst[i] = A_BYTES + swz(r, c);                                         \
        bsrc[i] = Bp + (long)r * K + c * 8;                                    \
    }                                                                          \
    const int q8 = lane >> 3, rr = lane & 7;                                   \
    const int rA = wm * 32 + (q8 & 1) * 8 + rr;                                \
    const int xA = (rA >> 1) & 3;                                              \
    const int cA = q8 >> 1;                                                    \
    const int rB = wn * 64 + (q8 >> 1) * 8 + rr;                               \
    const int xB = (rB >> 1) & 3;                                              \
    const int cB = q8 & 1;

#define ISSUE(kt)                                                              \
    do {                                                                       \
        const uint32_t _s = sb + ((kt) % 3) * STG;                             \
        const long _ko = (long)(kt) * 32;                                      \
        CP16(_s + adst[0], asrc[0] + _ko);                                     \
        CP16(_s + adst[1], asrc[1] + _ko);                                     \
        CP16(_s + bdst[0], bsrc[0] + _ko);                                     \
        CP16(_s + bdst[1], bsrc[1] + _ko);                                     \
        CP_COMMIT();                                                           \
    } while (0)

#define MAINLOOP()                                                             \
    ISSUE(0);                                                                  \
    ISSUE(1);                                                                  \
    const int nCh = K / 32;                                                    \
    for (int kt = 0; kt < nCh; kt++) {                                         \
        if (kt + 1 < nCh) CP_WAIT1(); else CP_WAIT0();                         \
        __syncthreads();                                                       \
        const uint32_t sbase = sb + (kt % 3) * STG;                            \
        _Pragma("unroll")                                                      \
        for (int s = 0; s < 2; s++) {                                          \
            uint32_t af[2][4];                                                 \
            _Pragma("unroll")                                                  \
            for (int mi = 0; mi < 2; mi++)                                     \
                ldsm4(af[mi], sbase + (uint32_t)((rA + mi * 16) * 64) +        \
                              (uint32_t)((((2 * s + cA) ^ xA)) << 4));         \
            _Pragma("unroll")                                                  \
            for (int nip = 0; nip < 4; nip++) {                                \
                uint32_t t4[4];                                                \
                ldsm4(t4, sbase + A_BYTES + (uint32_t)((rB + nip * 16) * 64) + \
                          (uint32_t)((((2 * s + cB) ^ xB)) << 4));             \
                _Pragma("unroll")                                              \
                for (int mi = 0; mi < 2; mi++) mma_f16(acc[mi][2 * nip],     af[mi], &t4[0]); \
                _Pragma("unroll")                                              \
                for (int mi = 0; mi < 2; mi++) mma_f16(acc[mi][2 * nip + 1], af[mi], &t4[2]); \
            }                                                                  \
        }                                                                      \
        if (kt + 2 < nCh) ISSUE(kt + 2);                                       \
    }

// ---------------- f16-in / f32-acc GEMM, fused epilogues ----------------
template <int EPI, bool OUTH>
__global__ void __launch_bounds__(NTHR, 2)
gemmv6(const __half* __restrict__ A, const __half* __restrict__ A2,
       const __half* __restrict__ B, void* __restrict__ Cv, void* __restrict__ Cv2,
       int M, int N, int K, long sA, long sB, long sC,
       const float* __restrict__ vec, long sVec,
       const float* __restrict__ add, long sAdd, float scale,
       float* __restrict__ part)
{
    const __half* Abase = A;
    void* Cbase = Cv;
    if (EPI == EPI_PROJ && blockIdx.z == 1) { Abase = A2; Cbase = Cv2; }
    const __half* Ap = Abase + (long)blockIdx.z * sA + (long)(blockIdx.y * BM) * K;
    const __half* Bp = B + (long)blockIdx.z * sB + (long)(blockIdx.x * BN) * K;

    GEMM_SETUP();

    float acc[2][8][4];
#pragma unroll
    for (int mi = 0; mi < 2; mi++)
#pragma unroll
        for (int ni = 0; ni < 8; ni++)
#pragma unroll
            for (int e = 0; e < 4; e++) acc[mi][ni][e] = 0.f;

    MAINLOOP();

    const float* vv = vec ? vec + (long)z * sVec : nullptr;
    const long cBase = (long)z * sC;

    if (EPI == EPI_EXP) {
        float rsl[2][2] = {{0.f, 0.f}, {0.f, 0.f}};
#pragma unroll
        for (int mi = 0; mi < 2; mi++) {
            const int r0 = blockIdx.y * BM + wm * 32 + mi * 16 + (lane >> 2);
#pragma unroll
            for (int ni = 0; ni < 8; ni++) {
                const int c = blockIdx.x * BN + wn * 64 + ni * 8 + (lane & 3) * 2;
                const float m0 = vv[c], m1 = vv[c + 1];
#pragma unroll
                for (int p = 0; p < 2; p++) {
                    const int r = r0 + p * 8;
                    float e0 = (m0 == 0.f) ? 0.f : expf(acc[mi][ni][p * 2 + 0] * scale);
                    float e1 = (m1 == 0.f) ? 0.f : expf(acc[mi][ni][p * 2 + 1] * scale);
                    __half2 h = __floats2half2_rn(e0, e1);
                    *(__half2*)((__half*)Cv + cBase + (long)r * N + c) = h;
                    float2 fr = __half22float2(h);
                    rsl[mi][p] += fr.x + fr.y;
                }
            }
        }
        float* rsf = (float*)(smem + (nCh % 3) * STG);
#pragma unroll
        for (int mi = 0; mi < 2; mi++)
#pragma unroll
            for (int p = 0; p < 2; p++) {
                float s = rsl[mi][p];
                s += __shfl_xor_sync(0xffffffffu, s, 1);
                s += __shfl_xor_sync(0xffffffffu, s, 2);
                if ((lane & 3) == 0)
                    rsf[(wm * 32 + mi * 16 + p * 8 + (lane >> 2)) * 2 + wn] = s;
            }
        __syncthreads();
        if (tid < BM) {
            float s = rsf[tid * 2] + rsf[tid * 2 + 1];
            part[((long)z * TT + blockIdx.y * BM + tid) * 16 + blockIdx.x] = s;
        }
        return;
    }

    const float* adb = add ? add + (long)z * sAdd : nullptr;

#pragma unroll
    for (int mi = 0; mi < 2; mi++) {
        const int r0 = blockIdx.y * BM + wm * 32 + mi * 16 + (lane >> 2);
        float rowS[2];
        if (EPI == EPI_CTX) { rowS[0] = vv[r0]; rowS[1] = vv[r0 + 8]; }
#pragma unroll
        for (int ni = 0; ni < 8; ni++) {
            const int c = blockIdx.x * BN + wn * 64 + ni * 8 + (lane & 3) * 2;
#pragma unroll
            for (int p = 0; p < 2; p++) {
                const int r = r0 + p * 8;
                float v0 = acc[mi][ni][p * 2 + 0];
                float v1 = acc[mi][ni][p * 2 + 1];
                if (EPI == EPI_PROJ) {
                    v0 = fmaxf(v0, 0.f); v1 = fmaxf(v1, 0.f);
                    if (z == 0) { v0 *= vv[c]; v1 *= vv[c + 1]; }
                }
                if (EPI == EPI_CTX) {
                    float2 a2 = *(const float2*)(adb + (long)r * N + c);
                    v0 = v0 * rowS[p] + a2.x;
                    v1 = v1 * rowS[p] + a2.y;
                }
                if (EPI == EPI_BIAS_RELU) { v0 = fmaxf(v0 + vv[c], 0.f); v1 = fmaxf(v1 + vv[c + 1], 0.f); }
                if (EPI == EPI_BIAS)      { v0 += vv[c]; v1 += vv[c + 1]; }
                if (OUTH) {
                    __half* op = (__half*)Cbase + cBase + (long)r * N + c;
                    *(__half2*)op = __floats2half2_rn(v0, v1);
                } else {
                    float* op = (float*)Cbase + cBase + (long)r * N + c;
                    *(float2*)op = make_float2(v0, v1);
                }
            }
        }
    }
}

// ---------------- invs: qmask/rowsum ----------------
__global__ __launch_bounds__(256)
void invs_k(const float* __restrict__ part, const float* __restrict__ qmask,
            float* __restrict__ invs)
{
    const int i = blockIdx.x * 256 + threadIdx.x;
    float s = 0.f;
#pragma unroll
    for (int j = 0; j < 16; j++) s += part[(long)i * 16 + j];
    invs[i] = qmask[i] / s;
}

// ---------------- Q convert: f32 -> f16, plus fp32 copy to output ----------------
__global__ __launch_bounds__(256)
void convq_k(const float* __restrict__ in, __half* __restrict__ out, float* __restrict__ outc)
{
    const int i = blockIdx.x * 256 + threadIdx.x;
    float4 v = ((const float4*)in)[i];
    __half2* o = (__half2*)out + (long)i * 2;
    o[0] = __floats2half2_rn(v.x, v.y);
    o[1] = __floats2half2_rn(v.z, v.w);
    ((float4*)outc)[i] = v;
}

// ---------------- K convert + transpose ----------------
__global__ __launch_bounds__(256)
void convkt_k(const float* __restrict__ in, __half* __restrict__ lin, __half* __restrict__ tr,
              int R, int C, long sIn, long sOut)
{
    __shared__ float t[32][33];
    const long zi = (long)blockIdx.z * sIn, zo = (long)blockIdx.z * sOut;
    const int c0 = blockIdx.x * 32, r0 = blockIdx.y * 32;
    const int tx = threadIdx.x, ty = threadIdx.y;
#pragma unroll
    for (int i = ty; i < 32; i += 8) {
        float v = in[zi + (long)(r0 + i) * C + c0 + tx];
        t[i][tx] = v;
        lin[zi + (long)(r0 + i) * C + c0 + tx] = __float2half(v);
    }
    __syncthreads();
#pragma unroll
    for (int i = ty; i < 32; i += 8)
        tr[zo + (long)(c0 + i) * R + r0 + tx] = __float2half(t[tx][i]);
}

// ---------------- batched square transpose f32 -> f16: three matrices ----------------
__global__ __launch_bounds__(256)
void transp3_k(const float* __restrict__ s0, const float* __restrict__ s1,
               const float* __restrict__ s2,
               __half* __restrict__ d0, __half* __restrict__ d1, __half* __restrict__ d2)
{
    __shared__ float t[32][33];
    const float* in  = blockIdx.z == 0 ? s0 : (blockIdx.z == 1 ? s1 : s2);
    __half* out      = blockIdx.z == 0 ? d0 : (blockIdx.z == 1 ? d1 : d2);
    const int c0 = blockIdx.x * 32, r0 = blockIdx.y * 32;
    const int tx = threadIdx.x, ty = threadIdx.y;
#pragma unroll
    for (int i = ty; i < 32; i += 8)
        t[i][tx] = in[(long)(r0 + i) * CH + c0 + tx];
    __syncthreads();
#pragma unroll
    for (int i = ty; i < 32; i += 8)
        out[(long)(c0 + i) * CH + r0 + tx] = __float2half(t[tx][i]);
}

// ---------------- LayerNorm: fp32 in -> f16 out ----------------
__global__ __launch_bounds__(256)
void ln_k(const float* __restrict__ in, __half* __restrict__ out,
          const float* __restrict__ gamma, const float* __restrict__ beta)
{
    __shared__ float sh[8];
    const long row = blockIdx.x;
    const float* p = in + row * CH;
    const int tid = threadIdx.x, lane = tid & 31, w = tid >> 5;
    const int c = tid * 4;

    float4 xv = *(const float4*)(p + c);
    float s = xv.x + xv.y + xv.z + xv.w;
#pragma unroll
    for (int o = 16; o; o >>= 1) s += __shfl_xor_sync(0xffffffffu, s, o);
    if (lane == 0) sh[w] = s;
    __syncthreads();
    float tot = 0.f;
#pragma unroll
    for (int i = 0; i < 8; i++) tot += sh[i];
    const float mu = tot * (1.f / CH);

    float d0 = xv.x - mu, d1 = xv.y - mu, d2 = xv.z - mu, d3 = xv.w - mu;
    float q = d0 * d0 + d1 * d1 + d2 * d2 + d3 * d3;
#pragma unroll
    for (int o = 16; o; o >>= 1) q += __shfl_xor_sync(0xffffffffu, q, o);
    __syncthreads();
    if (lane == 0) sh[w] = q;
    __syncthreads();
    float vtot = 0.f;
#pragma unroll
    for (int i = 0; i < 8; i++) vtot += sh[i];
    const float rstd = rsqrtf(vtot * (1.f / CH) + 1e-6f);

    float4 g  = *(const float4*)(gamma + c);
    float4 be = *(const float4*)(beta + c);
    __half2* o2 = (__half2*)(out + row * CH + c);
    o2[0] = __floats2half2_rn(d0 * rstd * g.x + be.x, d1 * rstd * g.y + be.y);
    o2[1] = __floats2half2_rn(d2 * rstd * g.z + be.z, d3 * rstd * g.w + be.w);
}

// ---------------- launch ----------------
extern "C" void kernel_launch(void* const* d_in, const int* in_sizes, int n_in,
                              void* d_out, int out_size)
{
    const float* Q     = (const float*)d_in[0];
    const float* Kk    = (const float*)d_in[1];
    const float* kmask = (const float*)d_in[2];
    const float* qmask = (const float*)d_in[3];
    const float* u     = (const float*)d_in[4];
    const float* dd    = (const float*)d_in[5];
    const float* W1    = (const float*)d_in[6];
    const float* b1    = (const float*)d_in[7];
    const float* W2    = (const float*)d_in[8];
    const float* b2    = (const float*)d_in[9];
    const float* gamma = (const float*)d_in[10];
    const float* beta  = (const float*)d_in[11];

    __half *hQ, *hK, *hKT, *hUT, *hW1T, *hW2T, *f1h, *f2h, *hS, *hLN, *hH;
    float  *ctx, *part, *invs;
    cudaGetSymbolAddress((void**)&hQ,  g_hQ);
    cudaGetSymbolAddress((void**)&hK,  g_hK);
    cudaGetSymbolAddress((void**)&hKT, g_hKT);
    cudaGetSymbolAddress((void**)&hUT, g_hUT);
    cudaGetSymbolAddress((void**)&hW1T, g_hW1T);
    cudaGetSymbolAddress((void**)&hW2T, g_hW2T);
    cudaGetSymbolAddress((void**)&f1h, g_f1h);
    cudaGetSymbolAddress((void**)&f2h, g_f2h);
    cudaGetSymbolAddress((void**)&hS,  g_hS);
    cudaGetSymbolAddress((void**)&ctx, g_ctx);
    cudaGetSymbolAddress((void**)&hLN, g_hLN);
    cudaGetSymbolAddress((void**)&hH,  g_hH);
    cudaGetSymbolAddress((void**)&part, g_part);
    cudaGetSymbolAddress((void**)&invs, g_invs);

    const long TC  = (long)TT * CH;
    const long TTl = (long)TT * TT;

    float* out2 = (float*)d_out;
    float* outq = (float*)d_out;
    if ((long)out_size >= 2 * (long)NTC) out2 = (float*)d_out + NTC;

    cudaFuncSetAttribute(gemmv6<EPI_PROJ, true>,      cudaFuncAttributeMaxDynamicSharedMemorySize, SMEM_G);
    cudaFuncSetAttribute(gemmv6<EPI_EXP, true>,       cudaFuncAttributeMaxDynamicSharedMemorySize, SMEM_G);
    cudaFuncSetAttribute(gemmv6<EPI_CTX, false>,      cudaFuncAttributeMaxDynamicSharedMemorySize, SMEM_G);
    cudaFuncSetAttribute(gemmv6<EPI_BIAS_RELU, true>, cudaFuncAttributeMaxDynamicSharedMemorySize, SMEM_G);
    cudaFuncSetAttribute(gemmv6<EPI_BIAS, false>,     cudaFuncAttributeMaxDynamicSharedMemorySize, SMEM_G);

    // ---- conversions ----
    convq_k<<<NTC / 1024, 256>>>(Q, hQ, outq);                                        // 1
    convkt_k<<<dim3(CH / 32, TT / 32, BB), dim3(32, 8)>>>(Kk, hK, hKT, TT, CH, TC, TC); // 2
    transp3_k<<<dim3(CH / 32, CH / 32, 3), dim3(32, 8)>>>(u, W1, W2, hUT, hW1T, hW2T);  // 3

    // ---- 1+2) f1 = relu(Q@u)*d ; f2 = relu(K@u)  (merged, grid.z=2) ----             4 (profiled?)
    gemmv6<EPI_PROJ, true><<<dim3(CH / BN, BB * TT / BM, 2), NTHR, SMEM_G>>>(
        hQ, hK, hUT, f1h, f2h, BB * TT, CH, CH, 0, 0, 0, dd, 0, nullptr, 0, 0.f, nullptr);

    // ---- 3) expS = exp((f1 @ f2^T)/32) masked -> f16, + row partial sums ----
    gemmv6<EPI_EXP, true><<<dim3(TT / BN, TT / BM, BB), NTHR, SMEM_G>>>(
        f1h, nullptr, f2h, hS, nullptr, TT, TT, CH, TC, TC, TTl, kmask, TT, nullptr, 0,
        1.0f / 32.0f, part);

    // ---- 4) invs = qmask / rowsum ----
    invs_k<<<BB * TT / 256, 256>>>(part, qmask, invs);

    // ---- 5) ctx = (expS @ K) * invs[row] + Q  (fp32 out) ----
    gemmv6<EPI_CTX, false><<<dim3(CH / BN, TT / BM, BB), NTHR, SMEM_G>>>(
        hS, nullptr, hKT, ctx, nullptr, TT, CH, TT, TTl, TC, TC, invs, TT, Q, TC, 0.f, nullptr);

    // ---- 6) LayerNorm -> f16 ----
    ln_k<<<BB * TT, 256>>>(ctx, hLN, gamma, beta);

    // ---- 7) h = relu(LN @ W1 + b1) -> f16 ----
    gemmv6<EPI_BIAS_RELU, true><<<dim3(CH / BN, BB * TT / BM, 1), NTHR, SMEM_G>>>(
        hLN, nullptr, hW1T, hH, nullptr, BB * TT, CH, CH, 0, 0, 0, b1, 0, nullptr, 0, 0.f, nullptr);

    // ---- 8) out2 = h @ W2 + b2 (fp32 out) ----
    gemmv6<EPI_BIAS, false><<<dim3(CH / BN, BB * TT / BM, 1), NTHR, SMEM_G>>>(
        hH, nullptr, hW2T, out2, nullptr, BB * TT, CH, CH, 0, 0, 0, b2, 0, nullptr, 0, 0.f, nullptr);
}

// round 11
// speedup vs baseline: 1.2506x; 1.0739x over previous
#include <cuda_runtime.h>
#include <cuda_fp16.h>
#include <math.h>
#include <stdint.h>

#define BB  8
#define TT  2048
#define CH  1024

#define NTC   (BB * TT * CH)              // 16,777,216
#define NTT   ((size_t)BB * TT * TT)      // 33,554,432

// ---------------- scratch (no allocations allowed) ----------------
__device__ __half g_hQ [NTC];
__device__ __half g_hK [NTC];
__device__ __half g_hKT[NTC];             // per-batch [CH][TT]
__device__ __half g_hUT [CH * CH];
__device__ __half g_hW1T[CH * CH];
__device__ __half g_hW2T[CH * CH];
__device__ __half g_f1h[NTC];
__device__ __half g_f2h[NTC];
__device__ __half g_hS [NTT];             // f16 exp(scores)
__device__ float  g_part[BB * TT * 16];
__device__ float  g_invs[BB * TT];
__device__ float  g_ctx[NTC];
__device__ __half g_hLN[NTC];
__device__ __half g_hH [NTC];

enum { EPI_PROJ = 0, EPI_EXP, EPI_CTX, EPI_BIAS_RELU, EPI_BIAS };

// ---------------- PTX helpers ----------------
__device__ __forceinline__ uint32_t smem_u32(const void* p) {
    uint32_t a;
    asm("{ .reg .u64 t; cvta.to.shared.u64 t, %1; cvt.u32.u64 %0, t; }" : "=r"(a) : "l"(p));
    return a;
}
__device__ __forceinline__ void ldsm4(uint32_t* r, uint32_t addr) {
    asm volatile("ldmatrix.sync.aligned.m8n8.x4.shared.b16 {%0,%1,%2,%3}, [%4];"
        : "=r"(r[0]), "=r"(r[1]), "=r"(r[2]), "=r"(r[3]) : "r"(addr));
}
__device__ __forceinline__ void mma_f16(float* d, const uint32_t* a, const uint32_t* b) {
    asm volatile(
        "mma.sync.aligned.m16n8k16.row.col.f32.f16.f16.f32 "
        "{%0,%1,%2,%3}, {%4,%5,%6,%7}, {%8,%9}, {%0,%1,%2,%3};"
        : "+f"(d[0]), "+f"(d[1]), "+f"(d[2]), "+f"(d[3])
        : "r"(a[0]), "r"(a[1]), "r"(a[2]), "r"(a[3]), "r"(b[0]), "r"(b[1]));
}
#define CP16(dst, src) \
    asm volatile("cp.async.cg.shared.global [%0], [%1], 16;" :: "r"(dst), "l"(src) : "memory")
#define CP_COMMIT()  asm volatile("cp.async.commit_group;" ::: "memory")
#define CP_WAIT1()   asm volatile("cp.async.wait_group 1;" ::: "memory")
#define CP_WAIT0()   asm volatile("cp.async.wait_group 0;" ::: "memory")

// swizzled offset within a k32 subtile: rows of 64B (32 halves), 16B column c (0..3)
__device__ __forceinline__ uint32_t swz(int row, int c) {
    return (uint32_t)(row * 64 + (((c) ^ ((row >> 1) & 3)) << 4));
}

// CTA tile 128x128, STAGE = K64 (two k32 subtiles), 3-stage cp.async ring,
// 8 warps (4m x 2n) of 32x64, 256 threads, 2 CTAs/SM.
#define BM 128
#define BN 128
#define A_BYTES (BM * 64)                 // 8192 per subtile
#define B_BYTES (BN * 64)                 // 8192 per subtile
#define SUBSTG  (A_BYTES + B_BYTES)       // 16384
#define STAGE   (2 * SUBSTG)              // 32768 (K=64)
#define SMEM_G  (3 * STAGE)               // 98304
#define NTHR    256

#define GEMM_SETUP()                                                           \
    extern __shared__ char smem[];                                             \
    const uint32_t sb = smem_u32(smem);                                        \
    const int tid = threadIdx.x, lane = tid & 31, warp = tid >> 5;             \
    const int wm = warp >> 1, wn = warp & 1;                                   \
    const int z = blockIdx.z;                                                  \
    uint32_t adst[2], bdst[2];                                                 \
    const __half* asrc[2];                                                     \
    const __half* bsrc[2];                                                     \
    _Pragma("unroll")                                                          \
    for (int i = 0; i < 2; i++) {                                              \
        int q = tid + i * NTHR, r = q >> 2, c = q & 3;                         \
        adst[i] = swz(r, c);                                                   \
        asrc[i] = Ap + (long)r * K + c * 8;                                    \
        bdst[i] = A_BYTES + swz(r, c);                                         \
        bsrc[i] = Bp + (long)r * K + c * 8;                                    \
    }                                                                          \
    const int q8 = lane >> 3, rr = lane & 7;                                   \
    const int rA = wm * 32 + (q8 & 1) * 8 + rr;                                \
    const int xA = (rA >> 1) & 3;                                              \
    const int cA = q8 >> 1;                                                    \
    const int rB = wn * 64 + (q8 >> 1) * 8 + rr;                               \
    const int xB = (rB >> 1) & 3;                                              \
    const int cB = q8 & 1;

// one stage = K64: two k32 subtiles, single commit
#define ISSUE(st)                                                              \
    do {                                                                       \
        const uint32_t _s = sb + ((st) % 3) * STAGE;                           \
        _Pragma("unroll")                                                      \
        for (int _sub = 0; _sub < 2; _sub++) {                                 \
            const long _ko = (long)(st) * 64 + _sub * 32;                      \
            const uint32_t _d = _s + _sub * SUBSTG;                            \
            CP16(_d + adst[0], asrc[0] + _ko);                                 \
            CP16(_d + adst[1], asrc[1] + _ko);                                 \
            CP16(_d + bdst[0], bsrc[0] + _ko);                                 \
            CP16(_d + bdst[1], bsrc[1] + _ko);                                 \
        }                                                                      \
        CP_COMMIT();                                                           \
    } while (0)

#define MAINLOOP()                                                             \
    ISSUE(0);                                                                  \
    ISSUE(1);                                                                  \
    const int nSt = K / 64;                                                    \
    for (int st = 0; st < nSt; st++) {                                         \
        if (st + 1 < nSt) CP_WAIT1(); else CP_WAIT0();                         \
        __syncthreads();                                                       \
        const uint32_t stbase = sb + (st % 3) * STAGE;                         \
        _Pragma("unroll")                                                      \
        for (int sub = 0; sub < 2; sub++) {                                    \
            const uint32_t sbase = stbase + sub * SUBSTG;                      \
            _Pragma("unroll")                                                  \
            for (int s = 0; s < 2; s++) {                                      \
                uint32_t af[2][4];                                             \
                _Pragma("unroll")                                              \
                for (int mi = 0; mi < 2; mi++)                                 \
                    ldsm4(af[mi], sbase + (uint32_t)((rA + mi * 16) * 64) +    \
                                  (uint32_t)((((2 * s + cA) ^ xA)) << 4));     \
                _Pragma("unroll")                                              \
                for (int nip = 0; nip < 4; nip++) {                            \
                    uint32_t t4[4];                                            \
                    ldsm4(t4, sbase + A_BYTES + (uint32_t)((rB + nip * 16) * 64) + \
                              (uint32_t)((((2 * s + cB) ^ xB)) << 4));         \
                    _Pragma("unroll")                                          \
                    for (int mi = 0; mi < 2; mi++) mma_f16(acc[mi][2 * nip],     af[mi], &t4[0]); \
                    _Pragma("unroll")                                          \
                    for (int mi = 0; mi < 2; mi++) mma_f16(acc[mi][2 * nip + 1], af[mi], &t4[2]); \
                }                                                              \
            }                                                                  \
        }                                                                      \
        if (st + 2 < nSt) ISSUE(st + 2);                                       \
    }

// ---------------- f16-in / f32-acc GEMM, fused epilogues ----------------
template <int EPI, bool OUTH>
__global__ void __launch_bounds__(NTHR, 2)
gemmv7(const __half* __restrict__ A, const __half* __restrict__ A2,
       const __half* __restrict__ B, void* __restrict__ Cv, void* __restrict__ Cv2,
       int M, int N, int K, long sA, long sB, long sC,
       const float* __restrict__ vec, long sVec,
       const float* __restrict__ add, long sAdd, float scale,
       float* __restrict__ part)
{
    const __half* Abase = A;
    void* Cbase = Cv;
    if (EPI == EPI_PROJ && blockIdx.z == 1) { Abase = A2; Cbase = Cv2; }
    const __half* Ap = Abase + (long)blockIdx.z * sA + (long)(blockIdx.y * BM) * K;
    const __half* Bp = B + (long)blockIdx.z * sB + (long)(blockIdx.x * BN) * K;

    GEMM_SETUP();

    float acc[2][8][4];
#pragma unroll
    for (int mi = 0; mi < 2; mi++)
#pragma unroll
        for (int ni = 0; ni < 8; ni++)
#pragma unroll
            for (int e = 0; e < 4; e++) acc[mi][ni][e] = 0.f;

    MAINLOOP();

    const float* vv = vec ? vec + (long)z * sVec : nullptr;
    const long cBase = (long)z * sC;

    if (EPI == EPI_EXP) {
        float rsl[2][2] = {{0.f, 0.f}, {0.f, 0.f}};
#pragma unroll
        for (int mi = 0; mi < 2; mi++) {
            const int r0 = blockIdx.y * BM + wm * 32 + mi * 16 + (lane >> 2);
#pragma unroll
            for (int ni = 0; ni < 8; ni++) {
                const int c = blockIdx.x * BN + wn * 64 + ni * 8 + (lane & 3) * 2;
                const float m0 = vv[c], m1 = vv[c + 1];
#pragma unroll
                for (int p = 0; p < 2; p++) {
                    const int r = r0 + p * 8;
                    float e0 = (m0 == 0.f) ? 0.f : expf(acc[mi][ni][p * 2 + 0] * scale);
                    float e1 = (m1 == 0.f) ? 0.f : expf(acc[mi][ni][p * 2 + 1] * scale);
                    __half2 h = __floats2half2_rn(e0, e1);
                    *(__half2*)((__half*)Cv + cBase + (long)r * N + c) = h;
                    float2 fr = __half22float2(h);
                    rsl[mi][p] += fr.x + fr.y;
                }
            }
        }
        float* rsf = (float*)(smem + (nSt % 3) * STAGE);
#pragma unroll
        for (int mi = 0; mi < 2; mi++)
#pragma unroll
            for (int p = 0; p < 2; p++) {
                float s = rsl[mi][p];
                s += __shfl_xor_sync(0xffffffffu, s, 1);
                s += __shfl_xor_sync(0xffffffffu, s, 2);
                if ((lane & 3) == 0)
                    rsf[(wm * 32 + mi * 16 + p * 8 + (lane >> 2)) * 2 + wn] = s;
            }
        __syncthreads();
        if (tid < BM) {
            float s = rsf[tid * 2] + rsf[tid * 2 + 1];
            part[((long)z * TT + blockIdx.y * BM + tid) * 16 + blockIdx.x] = s;
        }
        return;
    }

    const float* adb = add ? add + (long)z * sAdd : nullptr;

#pragma unroll
    for (int mi = 0; mi < 2; mi++) {
        const int r0 = blockIdx.y * BM + wm * 32 + mi * 16 + (lane >> 2);
        float rowS[2];
        if (EPI == EPI_CTX) { rowS[0] = vv[r0]; rowS[1] = vv[r0 + 8]; }
#pragma unroll
        for (int ni = 0; ni < 8; ni++) {
            const int c = blockIdx.x * BN + wn * 64 + ni * 8 + (lane & 3) * 2;
#pragma unroll
            for (int p = 0; p < 2; p++) {
                const int r = r0 + p * 8;
                float v0 = acc[mi][ni][p * 2 + 0];
                float v1 = acc[mi][ni][p * 2 + 1];
                if (EPI == EPI_PROJ) {
                    v0 = fmaxf(v0, 0.f); v1 = fmaxf(v1, 0.f);
                    if (z == 0) { v0 *= vv[c]; v1 *= vv[c + 1]; }
                }
                if (EPI == EPI_CTX) {
                    float2 a2 = *(const float2*)(adb + (long)r * N + c);
                    v0 = v0 * rowS[p] + a2.x;
                    v1 = v1 * rowS[p] + a2.y;
                }
                if (EPI == EPI_BIAS_RELU) { v0 = fmaxf(v0 + vv[c], 0.f); v1 = fmaxf(v1 + vv[c + 1], 0.f); }
                if (EPI == EPI_BIAS)      { v0 += vv[c]; v1 += vv[c + 1]; }
                if (OUTH) {
                    __half* op = (__half*)Cbase + cBase + (long)r * N + c;
                    *(__half2*)op = __floats2half2_rn(v0, v1);
                } else {
                    float* op = (float*)Cbase + cBase + (long)r * N + c;
                    *(float2*)op = make_float2(v0, v1);
                }
            }
        }
    }
}

// ---------------- invs: qmask/rowsum ----------------
__global__ __launch_bounds__(256)
void invs_k(const float* __restrict__ part, const float* __restrict__ qmask,
            float* __restrict__ invs)
{
    const int i = blockIdx.x * 256 + threadIdx.x;
    float s = 0.f;
#pragma unroll
    for (int j = 0; j < 16; j++) s += part[(long)i * 16 + j];
    invs[i] = qmask[i] / s;
}

// ---------------- Q convert: f32 -> f16, plus fp32 copy to output ----------------
__global__ __launch_bounds__(256)
void convq_k(const float* __restrict__ in, __half* __restrict__ out, float* __restrict__ outc)
{
    const int i = blockIdx.x * 256 + threadIdx.x;
    float4 v = ((const float4*)in)[i];
    __half2* o = (__half2*)out + (long)i * 2;
    o[0] = __floats2half2_rn(v.x, v.y);
    o[1] = __floats2half2_rn(v.z, v.w);
    ((float4*)outc)[i] = v;
}

// ---------------- K convert + transpose ----------------
__global__ __launch_bounds__(256)
void convkt_k(const float* __restrict__ in, __half* __restrict__ lin, __half* __restrict__ tr,
              int R, int C, long sIn, long sOut)
{
    __shared__ float t[32][33];
    const long zi = (long)blockIdx.z * sIn, zo = (long)blockIdx.z * sOut;
    const int c0 = blockIdx.x * 32, r0 = blockIdx.y * 32;
    const int tx = threadIdx.x, ty = threadIdx.y;
#pragma unroll
    for (int i = ty; i < 32; i += 8) {
        float v = in[zi + (long)(r0 + i) * C + c0 + tx];
        t[i][tx] = v;
        lin[zi + (long)(r0 + i) * C + c0 + tx] = __float2half(v);
    }
    __syncthreads();
#pragma unroll
    for (int i = ty; i < 32; i += 8)
        tr[zo + (long)(c0 + i) * R + r0 + tx] = __float2half(t[tx][i]);
}

// ---------------- batched square transpose f32 -> f16: three matrices ----------------
__global__ __launch_bounds__(256)
void transp3_k(const float* __restrict__ s0, const float* __restrict__ s1,
               const float* __restrict__ s2,
               __half* __restrict__ d0, __half* __restrict__ d1, __half* __restrict__ d2)
{
    __shared__ float t[32][33];
    const float* in  = blockIdx.z == 0 ? s0 : (blockIdx.z == 1 ? s1 : s2);
    __half* out      = blockIdx.z == 0 ? d0 : (blockIdx.z == 1 ? d1 : d2);
    const int c0 = blockIdx.x * 32, r0 = blockIdx.y * 32;
    const int tx = threadIdx.x, ty = threadIdx.y;
#pragma unroll
    for (int i = ty; i < 32; i += 8)
        t[i][tx] = in[(long)(r0 + i) * CH + c0 + tx];
    __syncthreads();
#pragma unroll
    for (int i = ty; i < 32; i += 8)
        out[(long)(c0 + i) * CH + r0 + tx] = __float2half(t[tx][i]);
}

// ---------------- LayerNorm: fp32 in -> f16 out ----------------
__global__ __launch_bounds__(256)
void ln_k(const float* __restrict__ in, __half* __restrict__ out,
          const float* __restrict__ gamma, const float* __restrict__ beta)
{
    __shared__ float sh[8];
    const long row = blockIdx.x;
    const float* p = in + row * CH;
    const int tid = threadIdx.x, lane = tid & 31, w = tid >> 5;
    const int c = tid * 4;

    float4 xv = *(const float4*)(p + c);
    float s = xv.x + xv.y + xv.z + xv.w;
#pragma unroll
    for (int o = 16; o; o >>= 1) s += __shfl_xor_sync(0xffffffffu, s, o);
    if (lane == 0) sh[w] = s;
    __syncthreads();
    float tot = 0.f;
#pragma unroll
    for (int i = 0; i < 8; i++) tot += sh[i];
    const float mu = tot * (1.f / CH);

    float d0 = xv.x - mu, d1 = xv.y - mu, d2 = xv.z - mu, d3 = xv.w - mu;
    float q = d0 * d0 + d1 * d1 + d2 * d2 + d3 * d3;
#pragma unroll
    for (int o = 16; o; o >>= 1) q += __shfl_xor_sync(0xffffffffu, q, o);
    __syncthreads();
    if (lane == 0) sh[w] = q;
    __syncthreads();
    float vtot = 0.f;
#pragma unroll
    for (int i = 0; i < 8; i++) vtot += sh[i];
    const float rstd = rsqrtf(vtot * (1.f / CH) + 1e-6f);

    float4 g  = *(const float4*)(gamma + c);
    float4 be = *(const float4*)(beta + c);
    __half2* o2 = (__half2*)(out + row * CH + c);
    o2[0] = __floats2half2_rn(d0 * rstd * g.x + be.x, d1 * rstd * g.y + be.y);
    o2[1] = __floats2half2_rn(d2 * rstd * g.z + be.z, d3 * rstd * g.w + be.w);
}

// ---------------- launch ----------------
extern "C" void kernel_launch(void* const* d_in, const int* in_sizes, int n_in,
                              void* d_out, int out_size)
{
    const float* Q     = (const float*)d_in[0];
    const float* Kk    = (const float*)d_in[1];
    const float* kmask = (const float*)d_in[2];
    const float* qmask = (const float*)d_in[3];
    const float* u     = (const float*)d_in[4];
    const float* dd    = (const float*)d_in[5];
    const float* W1    = (const float*)d_in[6];
    const float* b1    = (const float*)d_in[7];
    const float* W2    = (const float*)d_in[8];
    const float* b2    = (const float*)d_in[9];
    const float* gamma = (const float*)d_in[10];
    const float* beta  = (const float*)d_in[11];

    __half *hQ, *hK, *hKT, *hUT, *hW1T, *hW2T, *f1h, *f2h, *hS, *hLN, *hH;
    float  *ctx, *part, *invs;
    cudaGetSymbolAddress((void**)&hQ,  g_hQ);
    cudaGetSymbolAddress((void**)&hK,  g_hK);
    cudaGetSymbolAddress((void**)&hKT, g_hKT);
    cudaGetSymbolAddress((void**)&hUT, g_hUT);
    cudaGetSymbolAddress((void**)&hW1T, g_hW1T);
    cudaGetSymbolAddress((void**)&hW2T, g_hW2T);
    cudaGetSymbolAddress((void**)&f1h, g_f1h);
    cudaGetSymbolAddress((void**)&f2h, g_f2h);
    cudaGetSymbolAddress((void**)&hS,  g_hS);
    cudaGetSymbolAddress((void**)&ctx, g_ctx);
    cudaGetSymbolAddress((void**)&hLN, g_hLN);
    cudaGetSymbolAddress((void**)&hH,  g_hH);
    cudaGetSymbolAddress((void**)&part, g_part);
    cudaGetSymbolAddress((void**)&invs, g_invs);

    const long TC  = (long)TT * CH;
    const long TTl = (long)TT * TT;

    float* out2 = (float*)d_out;
    float* outq = (float*)d_out;
    if ((long)out_size >= 2 * (long)NTC) out2 = (float*)d_out + NTC;

    cudaFuncSetAttribute(gemmv7<EPI_PROJ, true>,      cudaFuncAttributeMaxDynamicSharedMemorySize, SMEM_G);
    cudaFuncSetAttribute(gemmv7<EPI_EXP, true>,       cudaFuncAttributeMaxDynamicSharedMemorySize, SMEM_G);
    cudaFuncSetAttribute(gemmv7<EPI_CTX, false>,      cudaFuncAttributeMaxDynamicSharedMemorySize, SMEM_G);
    cudaFuncSetAttribute(gemmv7<EPI_BIAS_RELU, true>, cudaFuncAttributeMaxDynamicSharedMemorySize, SMEM_G);
    cudaFuncSetAttribute(gemmv7<EPI_BIAS, false>,     cudaFuncAttributeMaxDynamicSharedMemorySize, SMEM_G);

    // ---- conversions ----
    convq_k<<<NTC / 1024, 256>>>(Q, hQ, outq);                                        // 1
    convkt_k<<<dim3(CH / 32, TT / 32, BB), dim3(32, 8)>>>(Kk, hK, hKT, TT, CH, TC, TC); // 2
    transp3_k<<<dim3(CH / 32, CH / 32, 3), dim3(32, 8)>>>(u, W1, W2, hUT, hW1T, hW2T);  // 3

    // ---- 1+2) f1 = relu(Q@u)*d ; f2 = relu(K@u)  (merged, grid.z=2) ----             4
    gemmv7<EPI_PROJ, true><<<dim3(CH / BN, BB * TT / BM, 2), NTHR, SMEM_G>>>(
        hQ, hK, hUT, f1h, f2h, BB * TT, CH, CH, 0, 0, 0, dd, 0, nullptr, 0, 0.f, nullptr);

    // ---- 3) expS = exp((f1 @ f2^T)/32) masked -> f16, + row partial sums ----
    gemmv7<EPI_EXP, true><<<dim3(TT / BN, TT / BM, BB), NTHR, SMEM_G>>>(
        f1h, nullptr, f2h, hS, nullptr, TT, TT, CH, TC, TC, TTl, kmask, TT, nullptr, 0,
        1.0f / 32.0f, part);

    // ---- 4) invs = qmask / rowsum ----
    invs_k<<<BB * TT / 256, 256>>>(part, qmask, invs);

    // ---- 5) ctx = (expS @ K) * invs[row] + Q  (fp32 out) ----
    gemmv7<EPI_CTX, false><<<dim3(CH / BN, TT / BM, BB), NTHR, SMEM_G>>>(
        hS, nullptr, hKT, ctx, nullptr, TT, CH, TT, TTl, TC, TC, invs, TT, Q, TC, 0.f, nullptr);

    // ---- 6) LayerNorm -> f16 ----
    ln_k<<<BB * TT, 256>>>(ctx, hLN, gamma, beta);

    // ---- 7) h = relu(LN @ W1 + b1) -> f16 ----
    gemmv7<EPI_BIAS_RELU, true><<<dim3(CH / BN, BB * TT / BM, 1), NTHR, SMEM_G>>>(
        hLN, nullptr, hW1T, hH, nullptr, BB * TT, CH, CH, 0, 0, 0, b1, 0, nullptr, 0, 0.f, nullptr);

    // ---- 8) out2 = h @ W2 + b2 (fp32 out) ----
    gemmv7<EPI_BIAS, false><<<dim3(CH / BN, BB * TT / BM, 1), NTHR, SMEM_G>>>(
        hH, nullptr, hW2T, out2, nullptr, BB * TT, CH, CH, 0, 0, 0, b2, 0, nullptr, 0, 0.f, nullptr);
}